// round 3
// baseline (speedup 1.0000x reference)
#include <cuda_runtime.h>
#include <math.h>

// Problem constants
#define BB  2
#define SS  2048
#define DD  2048
#define HH  16
#define DHH 128
#define MM  (BB*SS)          // 4096 rows
#define RSCALE 0.08838834764831843f   // 1/sqrt(128)

// Scratch (device globals — no allocation allowed)
__device__ float g_q[BB*HH*SS*DHH];     // [b,h,s,dh]
__device__ float g_k[BB*HH*SS*DHH];
__device__ float g_v[BB*HH*SS*DHH];
__device__ float g_attn[MM*DD];         // [b*s, d]

// ---------------------------------------------------------------------------
// SGEMM: C = A @ W^T + bias.  A:[M,K] row-major, W:[N,K] row-major.
// BM=BN=128, BK=16, 256 threads, 8x8 microtile.
// Register-staged double buffering: next K-tile is LDG'd into registers
// before the compute phase of the current tile, hiding global latency.
// MODE 0: scatter epilogue into [b,h,s,dh] layout; MODE 1: plain [M,N].
// ---------------------------------------------------------------------------
template<int MODE>
__global__ __launch_bounds__(256) void sgemm_tn(
    const float* __restrict__ A, const float* __restrict__ W,
    const float* __restrict__ bias, float* __restrict__ C,
    int M, int N, int K)
{
    __shared__ float As[16][132];   // transposed: As[k][m], padded
    __shared__ float Bs[16][132];

    const int bm = blockIdx.y * 128;
    const int bn = blockIdx.x * 128;
    const int tid = threadIdx.x;
    const int tx = tid & 15;        // col group
    const int ty = tid >> 4;        // row group

    // per-thread load coordinates (2 rows of A, 2 rows of W per tile)
    const int r0   = tid >> 1;              // 0..127 (it=0 row)
    const int q0_  = (tid & 1) * 8;         // unused split; keep 4-float quads:
    (void)q0_;
    // Use the same mapping as before: li = tid + it*256
    float4 pa[2], pb[2];

    auto load_tile = [&](int k0) {
        #pragma unroll
        for (int it = 0; it < 2; it++) {
            int li   = tid + it * 256;     // 0..511
            int row  = li >> 2;            // 0..127
            int quad = (li & 3) * 4;       // 0,4,8,12
            pa[it] = *(const float4*)&A[(size_t)(bm + row) * K + k0 + quad];
            pb[it] = *(const float4*)&W[(size_t)(bn + row) * K + k0 + quad];
        }
    };
    auto store_tile = [&]() {
        #pragma unroll
        for (int it = 0; it < 2; it++) {
            int li   = tid + it * 256;
            int row  = li >> 2;
            int quad = (li & 3) * 4;
            As[quad + 0][row] = pa[it].x; As[quad + 1][row] = pa[it].y;
            As[quad + 2][row] = pa[it].z; As[quad + 3][row] = pa[it].w;
            Bs[quad + 0][row] = pb[it].x; Bs[quad + 1][row] = pb[it].y;
            Bs[quad + 2][row] = pb[it].z; Bs[quad + 3][row] = pb[it].w;
        }
    };

    (void)r0;

    float acc[8][8];
    #pragma unroll
    for (int i = 0; i < 8; i++)
        #pragma unroll
        for (int j = 0; j < 8; j++) acc[i][j] = 0.f;

    load_tile(0);

    for (int k0 = 0; k0 < K; k0 += 16) {
        store_tile();
        __syncthreads();

        // prefetch next tile into registers (overlaps with compute below)
        if (k0 + 16 < K) load_tile(k0 + 16);

        #pragma unroll
        for (int kk = 0; kk < 16; kk++) {
            float a[8], b[8];
            *(float4*)&a[0] = *(const float4*)&As[kk][ty * 8];
            *(float4*)&a[4] = *(const float4*)&As[kk][ty * 8 + 4];
            *(float4*)&b[0] = *(const float4*)&Bs[kk][tx * 8];
            *(float4*)&b[4] = *(const float4*)&Bs[kk][tx * 8 + 4];
            #pragma unroll
            for (int i = 0; i < 8; i++)
                #pragma unroll
                for (int j = 0; j < 8; j++)
                    acc[i][j] = fmaf(a[i], b[j], acc[i][j]);
        }
        __syncthreads();
    }

    // epilogue
    #pragma unroll
    for (int i = 0; i < 8; i++) {
        int m = bm + ty * 8 + i;
        #pragma unroll
        for (int j = 0; j < 8; j++) {
            int n = bn + tx * 8 + j;
            float val = acc[i][j] + bias[n];
            if (MODE == 0) {
                int b_ = m >> 11;       // m / 2048
                int s_ = m & 2047;
                int h_ = n >> 7;        // n / 128
                int dh = n & 127;
                C[((size_t)(b_ * HH + h_) * SS + s_) * DHH + dh] = val;
            } else {
                C[(size_t)m * N + n] = val;
            }
        }
    }
}

// ---------------------------------------------------------------------------
// Flash attention (fp32, causal). Br=Bc=64, 256 threads.
// Grid: (qt=32, bh=32). Smem: Q,K,V [64][132], P [64][68], M/L/F [64].
// ---------------------------------------------------------------------------
#define FA_SMEM_FLOATS (64*132*3 + 64*68 + 64*3)
#define FA_SMEM_BYTES  (FA_SMEM_FLOATS * 4)

__global__ __launch_bounds__(256) void flash_kernel()
{
    extern __shared__ float sm[];
    float* sQ = sm;
    float* sK = sQ + 64 * 132;
    float* sV = sK + 64 * 132;
    float* sP = sV + 64 * 132;     // stride 68
    float* sM = sP + 64 * 68;
    float* sL = sM + 64;
    float* sF = sL + 64;

    const int bh = blockIdx.y;      // b*16 + h
    const int qt = blockIdx.x;
    const int q0 = qt * 64;
    const float* Qg = g_q + (size_t)bh * SS * DHH;
    const float* Kg = g_k + (size_t)bh * SS * DHH;
    const float* Vg = g_v + (size_t)bh * SS * DHH;

    const int tid = threadIdx.x;
    const int sr  = tid >> 4;   // 0..15: rows sr*4..sr*4+3
    const int sc  = tid & 15;   // 0..15: S cols sc*4.. / O cols sc*8..

    // load Q tile
    for (int li = tid; li < 64 * 32; li += 256) {
        int row = li >> 5;
        int c4  = (li & 31) * 4;
        *(float4*)&sQ[row * 132 + c4] = *(const float4*)&Qg[(size_t)(q0 + row) * DHH + c4];
    }
    if (tid < 64) { sM[tid] = -1e30f; sL[tid] = 0.f; }

    float o[4][8];
    #pragma unroll
    for (int i = 0; i < 4; i++)
        #pragma unroll
        for (int j = 0; j < 8; j++) o[i][j] = 0.f;

    for (int kt = 0; kt <= qt; kt++) {
        const int k0 = kt * 64;
        __syncthreads();   // protect sK/sV/sP reuse + first-iter init visibility

        for (int li = tid; li < 64 * 32; li += 256) {
            int row = li >> 5;
            int c4  = (li & 31) * 4;
            *(float4*)&sK[row * 132 + c4] = *(const float4*)&Kg[(size_t)(k0 + row) * DHH + c4];
            *(float4*)&sV[row * 132 + c4] = *(const float4*)&Vg[(size_t)(k0 + row) * DHH + c4];
        }
        __syncthreads();

        // S = Q K^T (4x4 microtile per thread)
        float s[4][4];
        #pragma unroll
        for (int i = 0; i < 4; i++)
            #pragma unroll
            for (int j = 0; j < 4; j++) s[i][j] = 0.f;

        for (int d = 0; d < 128; d += 4) {
            float qb[4][4], kb[4][4];
            #pragma unroll
            for (int i = 0; i < 4; i++)
                *(float4*)qb[i] = *(const float4*)&sQ[(sr * 4 + i) * 132 + d];
            #pragma unroll
            for (int j = 0; j < 4; j++)
                *(float4*)kb[j] = *(const float4*)&sK[(sc * 4 + j) * 132 + d];
            #pragma unroll
            for (int i = 0; i < 4; i++)
                #pragma unroll
                for (int j = 0; j < 4; j++)
                    #pragma unroll
                    for (int u = 0; u < 4; u++)
                        s[i][j] = fmaf(qb[i][u], kb[j][u], s[i][j]);
        }

        #pragma unroll
        for (int i = 0; i < 4; i++)
            #pragma unroll
            for (int j = 0; j < 4; j++) s[i][j] *= RSCALE;

        if (kt == qt) {
            #pragma unroll
            for (int i = 0; i < 4; i++)
                #pragma unroll
                for (int j = 0; j < 4; j++)
                    if (k0 + sc * 4 + j > q0 + sr * 4 + i) s[i][j] = -1e30f;
        }

        // online softmax: row reductions over 16 lanes (width 16)
        #pragma unroll
        for (int i = 0; i < 4; i++) {
            int row = sr * 4 + i;
            float rmax = fmaxf(fmaxf(s[i][0], s[i][1]), fmaxf(s[i][2], s[i][3]));
            #pragma unroll
            for (int off = 8; off >= 1; off >>= 1)
                rmax = fmaxf(rmax, __shfl_xor_sync(0xffffffffu, rmax, off, 16));
            float om = sM[row];
            float nm = fmaxf(om, rmax);
            float rsum = 0.f;
            #pragma unroll
            for (int j = 0; j < 4; j++) {
                float p = __expf(s[i][j] - nm);
                s[i][j] = p;
                rsum += p;
            }
            #pragma unroll
            for (int off = 8; off >= 1; off >>= 1)
                rsum += __shfl_xor_sync(0xffffffffu, rsum, off, 16);
            if (sc == 0) {
                float f = __expf(om - nm);
                sF[row] = f;
                sL[row] = sL[row] * f + rsum;
                sM[row] = nm;
            }
        }

        // stash P
        #pragma unroll
        for (int i = 0; i < 4; i++) {
            float4 p4 = make_float4(s[i][0], s[i][1], s[i][2], s[i][3]);
            *(float4*)&sP[(sr * 4 + i) * 68 + sc * 4] = p4;
        }
        __syncthreads();

        // rescale O, accumulate P@V
        #pragma unroll
        for (int i = 0; i < 4; i++) {
            float f = sF[sr * 4 + i];
            #pragma unroll
            for (int j = 0; j < 8; j++) o[i][j] *= f;
        }

        for (int jj = 0; jj < 64; jj += 4) {
            float pbuf[4][4];
            #pragma unroll
            for (int i = 0; i < 4; i++)
                *(float4*)pbuf[i] = *(const float4*)&sP[(sr * 4 + i) * 68 + jj];
            #pragma unroll
            for (int u = 0; u < 4; u++) {
                float4 v0 = *(const float4*)&sV[(jj + u) * 132 + sc * 8];
                float4 v1 = *(const float4*)&sV[(jj + u) * 132 + sc * 8 + 4];
                #pragma unroll
                for (int i = 0; i < 4; i++) {
                    float p = pbuf[i][u];
                    o[i][0] = fmaf(p, v0.x, o[i][0]);
                    o[i][1] = fmaf(p, v0.y, o[i][1]);
                    o[i][2] = fmaf(p, v0.z, o[i][2]);
                    o[i][3] = fmaf(p, v0.w, o[i][3]);
                    o[i][4] = fmaf(p, v1.x, o[i][4]);
                    o[i][5] = fmaf(p, v1.y, o[i][5]);
                    o[i][6] = fmaf(p, v1.z, o[i][6]);
                    o[i][7] = fmaf(p, v1.w, o[i][7]);
                }
            }
        }
    }

    // normalize + write to g_attn [b*s, d]
    const int b_ = bh >> 4;
    const int h_ = bh & 15;
    #pragma unroll
    for (int i = 0; i < 4; i++) {
        int row = sr * 4 + i;
        float inv = 1.f / sL[row];
        size_t base = (size_t)(b_ * SS + q0 + row) * DD + h_ * DHH + sc * 8;
        #pragma unroll
        for (int j = 0; j < 8; j++)
            g_attn[base + j] = o[i][j] * inv;
    }
}

// ---------------------------------------------------------------------------
// Launch
// ---------------------------------------------------------------------------
extern "C" void kernel_launch(void* const* d_in, const int* in_sizes, int n_in,
                              void* d_out, int out_size)
{
    (void)in_sizes; (void)n_in; (void)out_size;
    const float* x  = (const float*)d_in[0];
    // d_in[1] = causal mask (known statically, ignored)
    const float* wq = (const float*)d_in[2];
    const float* bq = (const float*)d_in[3];
    const float* wk = (const float*)d_in[4];
    const float* bk = (const float*)d_in[5];
    const float* wv = (const float*)d_in[6];
    const float* bv = (const float*)d_in[7];
    const float* wo = (const float*)d_in[8];
    const float* bo = (const float*)d_in[9];
    float* out = (float*)d_out;

    float *q, *k, *v, *attn;
    cudaGetSymbolAddress((void**)&q,    g_q);
    cudaGetSymbolAddress((void**)&k,    g_k);
    cudaGetSymbolAddress((void**)&v,    g_v);
    cudaGetSymbolAddress((void**)&attn, g_attn);

    cudaFuncSetAttribute(flash_kernel,
                         cudaFuncAttributeMaxDynamicSharedMemorySize,
                         FA_SMEM_BYTES);

    dim3 gproj(DD / 128, MM / 128);   // (16, 32)
    sgemm_tn<0><<<gproj, 256>>>(x, wq, bq, q, MM, DD, DD);
    sgemm_tn<0><<<gproj, 256>>>(x, wk, bk, k, MM, DD, DD);
    sgemm_tn<0><<<gproj, 256>>>(x, wv, bv, v, MM, DD, DD);

    flash_kernel<<<dim3(SS / 64, BB * HH), 256, FA_SMEM_BYTES>>>();

    sgemm_tn<1><<<gproj, 256>>>(attn, wo, bo, out, MM, DD, DD);
}

// round 10
// speedup vs baseline: 1.6161x; 1.6161x over previous
#include <cuda_runtime.h>
#include <cuda_bf16.h>
#include <cstdint>
#include <math.h>

// ---------------------------------------------------------------------------
// Problem constants
// ---------------------------------------------------------------------------
#define BB  2
#define SS  2048
#define DD  2048
#define HH  16
#define DHH 128
#define MM  (BB*SS)          // 4096
#define KP  6144             // tripled K for split-bf16
#define KP2 (KP*2)           // row stride in bytes
#define RSCALE 0.08838834764831843f

// ---------------------------------------------------------------------------
// Scratch (device globals — no allocation allowed)
// ---------------------------------------------------------------------------
__device__ float g_q[BB*HH*SS*DHH];
__device__ float g_k[BB*HH*SS*DHH];
__device__ float g_v[BB*HH*SS*DHH];
__device__ float g_attn[MM*DD];
__device__ __nv_bfloat16 g_x3[(size_t)MM*KP];   // x split  [hi|hi|lo]
__device__ __nv_bfloat16 g_w3q[(size_t)DD*KP];  // weights  [hi|lo|hi]
__device__ __nv_bfloat16 g_w3k[(size_t)DD*KP];
__device__ __nv_bfloat16 g_w3v[(size_t)DD*KP];
__device__ __nv_bfloat16 g_w3o[(size_t)DD*KP];
__device__ __nv_bfloat16 g_a3[(size_t)MM*KP];   // attn split [hi|hi|lo]

// ---------------------------------------------------------------------------
// PTX helpers — ONLY non-'a' features (ldmatrix, mma.sync, cp.async)
// ---------------------------------------------------------------------------
__device__ __forceinline__ uint32_t smem_to_u32(const void* p) {
    uint32_t a;
    asm("{ .reg .u64 t; cvta.to.shared.u64 t, %1; cvt.u32.u64 %0, t; }"
        : "=r"(a) : "l"(p));
    return a;
}
#define CP_ASYNC16(dst, src) \
    asm volatile("cp.async.cg.shared.global [%0], [%1], 16;" :: "r"(dst), "l"(src))
#define CP_COMMIT() asm volatile("cp.async.commit_group;" ::: "memory")
#define CP_WAIT1()  asm volatile("cp.async.wait_group 1;" ::: "memory")
#define LDSM_X4(r0,r1,r2,r3,addr) \
    asm volatile("ldmatrix.sync.aligned.m8n8.x4.shared.b16 {%0,%1,%2,%3},[%4];" \
        : "=r"(r0),"=r"(r1),"=r"(r2),"=r"(r3) : "r"(addr))
#define LDSM_X2(r0,r1,addr) \
    asm volatile("ldmatrix.sync.aligned.m8n8.x2.shared.b16 {%0,%1},[%2];" \
        : "=r"(r0),"=r"(r1) : "r"(addr))
#define MMA16816(d,a0,a1,a2,a3,b0,b1) \
    asm volatile("mma.sync.aligned.m16n8k16.row.col.f32.bf16.bf16.f32 " \
        "{%0,%1,%2,%3},{%4,%5,%6,%7},{%8,%9},{%0,%1,%2,%3};" \
        : "+f"((d)[0]),"+f"((d)[1]),"+f"((d)[2]),"+f"((d)[3]) \
        : "r"(a0),"r"(a1),"r"(a2),"r"(a3),"r"(b0),"r"(b1))

// ---------------------------------------------------------------------------
// Split pre-pass: fp32 [rows, 2048] -> bf16 [rows, 6144].
// bmode 0 (A side): [hi | hi | lo].  bmode 1 (B side): [hi | lo | hi].
// ---------------------------------------------------------------------------
__global__ void split3(const float* __restrict__ src, __nv_bfloat16* __restrict__ dst,
                       int rows, int bmode)
{
    int idx = blockIdx.x * blockDim.x + threadIdx.x;
    int total = rows * (DD / 4);
    for (; idx < total; idx += gridDim.x * blockDim.x) {
        int r  = idx >> 9;
        int c4 = (idx & 511) * 4;
        float4 v = *(const float4*)(src + (size_t)r * DD + c4);
        union { __nv_bfloat16 b[4]; uint64_t u; } H, L;
        H.b[0] = __float2bfloat16(v.x);
        H.b[1] = __float2bfloat16(v.y);
        H.b[2] = __float2bfloat16(v.z);
        H.b[3] = __float2bfloat16(v.w);
        L.b[0] = __float2bfloat16(v.x - __bfloat162float(H.b[0]));
        L.b[1] = __float2bfloat16(v.y - __bfloat162float(H.b[1]));
        L.b[2] = __float2bfloat16(v.z - __bfloat162float(H.b[2]));
        L.b[3] = __float2bfloat16(v.w - __bfloat162float(H.b[3]));
        __nv_bfloat16* row = dst + (size_t)r * KP;
        *(uint64_t*)&row[c4]        = H.u;
        *(uint64_t*)&row[2048 + c4] = bmode ? L.u : H.u;
        *(uint64_t*)&row[4096 + c4] = bmode ? H.u : L.u;
    }
}

// ---------------------------------------------------------------------------
// HMMA GEMM: C[M,N] = A3[M,KP] @ W3[N,KP]^T + bias (fp32 out).
// BM=BN=128, BK=32, 256 threads (8 warps, 2M x 4N), warp tile 64x32.
// 3-stage cp.async pipeline. MODE 0: scatter [b,h,s,dh]; MODE 1: [M,N].
// ---------------------------------------------------------------------------
#define NIT 192                 // KP / 32
#define STG_ELEMS (128*40)      // one stage of A or B (bf16 elems)
#define STG_BYTES (STG_ELEMS*2) // 10240
#define SB_OFF    (3*STG_BYTES)         // B region after 3 A stages
#define BIAS_OFF  (6*STG_BYTES)         // 61440
#define HG_SMEM   (BIAS_OFF + 512)      // 61952 bytes

template<int MODE>
__global__ __launch_bounds__(256) void hgemm(
    const __nv_bfloat16* __restrict__ A3,
    const __nv_bfloat16* __restrict__ W0, const __nv_bfloat16* __restrict__ W1,
    const __nv_bfloat16* __restrict__ W2,
    const float* __restrict__ b0, const float* __restrict__ b1, const float* __restrict__ b2,
    float* __restrict__ C0, float* __restrict__ C1, float* __restrict__ C2)
{
    extern __shared__ char smem[];
    const int tid  = threadIdx.x;
    const int wid  = tid >> 5, lane = tid & 31;
    const int wm   = wid >> 2;          // 0..1  (64 rows each)
    const int wn   = wid & 3;           // 0..3  (32 cols each)
    const int bn   = blockIdx.x * 128;
    const int bm   = blockIdx.y * 128;
    const int z    = blockIdx.z;
    const __nv_bfloat16* W = (z == 0) ? W0 : (z == 1) ? W1 : W2;
    const float* bias      = (z == 0) ? b0 : (z == 1) ? b1 : b2;
    float* C               = (z == 0) ? C0 : (z == 1) ? C1 : C2;

    const uint32_t sbase = smem_to_u32(smem);
    float* sBias = (float*)(smem + BIAS_OFF);
    if (tid < 128) sBias[tid] = bias[bn + tid];

    const char* Abase = (const char*)(A3 + (size_t)bm * KP);
    const char* Wbase = (const char*)(W  + (size_t)bn * KP);

    auto issue = [&](int it, int stg) {
        #pragma unroll
        for (int half = 0; half < 2; half++) {
            int idx = tid + half * 256;           // 0..511
            int row = idx >> 2;                   // 0..127
            int seg = idx & 3;                    // 16B segments
            uint32_t da = sbase + stg * STG_BYTES + row * 80 + seg * 16;
            CP_ASYNC16(da, Abase + (size_t)row * KP2 + (size_t)it * 64 + seg * 16);
            uint32_t db = sbase + SB_OFF + stg * STG_BYTES + row * 80 + seg * 16;
            CP_ASYNC16(db, Wbase + (size_t)row * KP2 + (size_t)it * 64 + seg * 16);
        }
    };

    float acc[4][4][4];
    #pragma unroll
    for (int i = 0; i < 4; i++)
        #pragma unroll
        for (int j = 0; j < 4; j++)
            #pragma unroll
            for (int r = 0; r < 4; r++) acc[i][j][r] = 0.f;

    issue(0, 0); CP_COMMIT();
    issue(1, 1); CP_COMMIT();

    // precomputed ldmatrix lane addressing
    const int a_row = lane & 15;             // row within 16
    const int a_coff = (lane >> 4) << 3;     // 0 or 8 (k offset)
    const int b_row = lane & 7;
    const int b_coff = ((lane >> 3) & 1) << 3;

    for (int it = 0; it < NIT; it++) {
        CP_WAIT1();
        __syncthreads();
        if (it + 2 < NIT) issue(it + 2, (it + 2) % 3);
        CP_COMMIT();

        const int stg = it % 3;
        const uint32_t aS = sbase + stg * STG_BYTES;
        const uint32_t bS = sbase + SB_OFF + stg * STG_BYTES;

        #pragma unroll
        for (int ks = 0; ks < 2; ks++) {
            uint32_t a[4][4], b[4][2];
            #pragma unroll
            for (int mi = 0; mi < 4; mi++) {
                uint32_t addr = aS + (wm * 64 + mi * 16 + a_row) * 80
                              + (ks * 16 + a_coff) * 2;
                LDSM_X4(a[mi][0], a[mi][1], a[mi][2], a[mi][3], addr);
            }
            #pragma unroll
            for (int ni = 0; ni < 4; ni++) {
                uint32_t addr = bS + (wn * 32 + ni * 8 + b_row) * 80
                              + (ks * 16 + b_coff) * 2;
                LDSM_X2(b[ni][0], b[ni][1], addr);
            }
            #pragma unroll
            for (int mi = 0; mi < 4; mi++)
                #pragma unroll
                for (int ni = 0; ni < 4; ni++)
                    MMA16816(acc[mi][ni], a[mi][0], a[mi][1], a[mi][2], a[mi][3],
                             b[ni][0], b[ni][1]);
        }
        __syncthreads();
    }

    // epilogue: fragment layout -> bias add -> float2 stores
    const int erow = lane >> 2;
    const int ecol = (lane & 3) * 2;
    #pragma unroll
    for (int mi = 0; mi < 4; mi++) {
        #pragma unroll
        for (int ni = 0; ni < 4; ni++) {
            int nloc = wn * 32 + ni * 8 + ecol;
            int n = bn + nloc;
            float bia0 = sBias[nloc], bia1 = sBias[nloc + 1];
            #pragma unroll
            for (int half = 0; half < 2; half++) {
                int m = bm + wm * 64 + mi * 16 + erow + half * 8;
                float2 v = make_float2(acc[mi][ni][half * 2]     + bia0,
                                       acc[mi][ni][half * 2 + 1] + bia1);
                if (MODE == 0) {
                    int b_ = m >> 11, s_ = m & 2047, h = n >> 7, dh = n & 127;
                    *(float2*)&C[((size_t)(b_ * HH + h) * SS + s_) * DHH + dh] = v;
                } else {
                    *(float2*)&C[(size_t)m * DD + n] = v;
                }
            }
        }
    }
}

// ---------------------------------------------------------------------------
// Flash attention (fp32, causal). Br=Bc=64, 256 threads. (unchanged, proven)
// ---------------------------------------------------------------------------
#define FA_SMEM_FLOATS (64*132*3 + 64*68 + 64*3)
#define FA_SMEM_BYTES  (FA_SMEM_FLOATS * 4)

__global__ __launch_bounds__(256) void flash_kernel()
{
    extern __shared__ float sm[];
    float* sQ = sm;
    float* sK = sQ + 64 * 132;
    float* sV = sK + 64 * 132;
    float* sP = sV + 64 * 132;
    float* sM = sP + 64 * 68;
    float* sL = sM + 64;
    float* sF = sL + 64;

    const int bh = blockIdx.y;
    const int qt = blockIdx.x;
    const int q0 = qt * 64;
    const float* Qg = g_q + (size_t)bh * SS * DHH;
    const float* Kg = g_k + (size_t)bh * SS * DHH;
    const float* Vg = g_v + (size_t)bh * SS * DHH;

    const int tid = threadIdx.x;
    const int sr  = tid >> 4;
    const int sc  = tid & 15;

    for (int li = tid; li < 64 * 32; li += 256) {
        int row = li >> 5;
        int c4  = (li & 31) * 4;
        *(float4*)&sQ[row * 132 + c4] = *(const float4*)&Qg[(size_t)(q0 + row) * DHH + c4];
    }
    if (tid < 64) { sM[tid] = -1e30f; sL[tid] = 0.f; }

    float o[4][8];
    #pragma unroll
    for (int i = 0; i < 4; i++)
        #pragma unroll
        for (int j = 0; j < 8; j++) o[i][j] = 0.f;

    for (int kt = 0; kt <= qt; kt++) {
        const int k0 = kt * 64;
        __syncthreads();

        for (int li = tid; li < 64 * 32; li += 256) {
            int row = li >> 5;
            int c4  = (li & 31) * 4;
            *(float4*)&sK[row * 132 + c4] = *(const float4*)&Kg[(size_t)(k0 + row) * DHH + c4];
            *(float4*)&sV[row * 132 + c4] = *(const float4*)&Vg[(size_t)(k0 + row) * DHH + c4];
        }
        __syncthreads();

        float s[4][4];
        #pragma unroll
        for (int i = 0; i < 4; i++)
            #pragma unroll
            for (int j = 0; j < 4; j++) s[i][j] = 0.f;

        for (int d = 0; d < 128; d += 4) {
            float qb[4][4], kb[4][4];
            #pragma unroll
            for (int i = 0; i < 4; i++)
                *(float4*)qb[i] = *(const float4*)&sQ[(sr * 4 + i) * 132 + d];
            #pragma unroll
            for (int j = 0; j < 4; j++)
                *(float4*)kb[j] = *(const float4*)&sK[(sc * 4 + j) * 132 + d];
            #pragma unroll
            for (int i = 0; i < 4; i++)
                #pragma unroll
                for (int j = 0; j < 4; j++)
                    #pragma unroll
                    for (int u = 0; u < 4; u++)
                        s[i][j] = fmaf(qb[i][u], kb[j][u], s[i][j]);
        }

        #pragma unroll
        for (int i = 0; i < 4; i++)
            #pragma unroll
            for (int j = 0; j < 4; j++) s[i][j] *= RSCALE;

        if (kt == qt) {
            #pragma unroll
            for (int i = 0; i < 4; i++)
                #pragma unroll
                for (int j = 0; j < 4; j++)
                    if (k0 + sc * 4 + j > q0 + sr * 4 + i) s[i][j] = -1e30f;
        }

        #pragma unroll
        for (int i = 0; i < 4; i++) {
            int rowi = sr * 4 + i;
            float rmax = fmaxf(fmaxf(s[i][0], s[i][1]), fmaxf(s[i][2], s[i][3]));
            #pragma unroll
            for (int off = 8; off >= 1; off >>= 1)
                rmax = fmaxf(rmax, __shfl_xor_sync(0xffffffffu, rmax, off, 16));
            float om = sM[rowi];
            float nm = fmaxf(om, rmax);
            float rsum = 0.f;
            #pragma unroll
            for (int j = 0; j < 4; j++) {
                float p = __expf(s[i][j] - nm);
                s[i][j] = p;
                rsum += p;
            }
            #pragma unroll
            for (int off = 8; off >= 1; off >>= 1)
                rsum += __shfl_xor_sync(0xffffffffu, rsum, off, 16);
            if (sc == 0) {
                float f = __expf(om - nm);
                sF[rowi] = f;
                sL[rowi] = sL[rowi] * f + rsum;
                sM[rowi] = nm;
            }
        }

        #pragma unroll
        for (int i = 0; i < 4; i++) {
            float4 p4 = make_float4(s[i][0], s[i][1], s[i][2], s[i][3]);
            *(float4*)&sP[(sr * 4 + i) * 68 + sc * 4] = p4;
        }
        __syncthreads();

        #pragma unroll
        for (int i = 0; i < 4; i++) {
            float f = sF[sr * 4 + i];
            #pragma unroll
            for (int j = 0; j < 8; j++) o[i][j] *= f;
        }

        for (int jj = 0; jj < 64; jj += 4) {
            float pbuf[4][4];
            #pragma unroll
            for (int i = 0; i < 4; i++)
                *(float4*)pbuf[i] = *(const float4*)&sP[(sr * 4 + i) * 68 + jj];
            #pragma unroll
            for (int u = 0; u < 4; u++) {
                float4 v0 = *(const float4*)&sV[(jj + u) * 132 + sc * 8];
                float4 v1 = *(const float4*)&sV[(jj + u) * 132 + sc * 8 + 4];
                #pragma unroll
                for (int i = 0; i < 4; i++) {
                    float p = pbuf[i][u];
                    o[i][0] = fmaf(p, v0.x, o[i][0]);
                    o[i][1] = fmaf(p, v0.y, o[i][1]);
                    o[i][2] = fmaf(p, v0.z, o[i][2]);
                    o[i][3] = fmaf(p, v0.w, o[i][3]);
                    o[i][4] = fmaf(p, v1.x, o[i][4]);
                    o[i][5] = fmaf(p, v1.y, o[i][5]);
                    o[i][6] = fmaf(p, v1.z, o[i][6]);
                    o[i][7] = fmaf(p, v1.w, o[i][7]);
                }
            }
        }
    }

    const int b_ = bh >> 4;
    const int h_ = bh & 15;
    #pragma unroll
    for (int i = 0; i < 4; i++) {
        int rowi = sr * 4 + i;
        float inv = 1.f / sL[rowi];
        size_t base = (size_t)(b_ * SS + q0 + rowi) * DD + h_ * DHH + sc * 8;
        #pragma unroll
        for (int j = 0; j < 8; j++)
            g_attn[base + j] = o[i][j] * inv;
    }
}

// ---------------------------------------------------------------------------
// Launch
// ---------------------------------------------------------------------------
extern "C" void kernel_launch(void* const* d_in, const int* in_sizes, int n_in,
                              void* d_out, int out_size)
{
    (void)in_sizes; (void)n_in; (void)out_size;
    const float* x  = (const float*)d_in[0];
    const float* wq = (const float*)d_in[2];
    const float* bq = (const float*)d_in[3];
    const float* wk = (const float*)d_in[4];
    const float* bk = (const float*)d_in[5];
    const float* wv = (const float*)d_in[6];
    const float* bv = (const float*)d_in[7];
    const float* wo = (const float*)d_in[8];
    const float* bo = (const float*)d_in[9];
    float* out = (float*)d_out;

    float *q, *k, *v, *attn;
    __nv_bfloat16 *x3, *w3q, *w3k, *w3v, *w3o, *a3;
    cudaGetSymbolAddress((void**)&q,    g_q);
    cudaGetSymbolAddress((void**)&k,    g_k);
    cudaGetSymbolAddress((void**)&v,    g_v);
    cudaGetSymbolAddress((void**)&attn, g_attn);
    cudaGetSymbolAddress((void**)&x3,   g_x3);
    cudaGetSymbolAddress((void**)&w3q,  g_w3q);
    cudaGetSymbolAddress((void**)&w3k,  g_w3k);
    cudaGetSymbolAddress((void**)&w3v,  g_w3v);
    cudaGetSymbolAddress((void**)&w3o,  g_w3o);
    cudaGetSymbolAddress((void**)&a3,   g_a3);

    cudaFuncSetAttribute(hgemm<0>, cudaFuncAttributeMaxDynamicSharedMemorySize, HG_SMEM);
    cudaFuncSetAttribute(hgemm<1>, cudaFuncAttributeMaxDynamicSharedMemorySize, HG_SMEM);
    cudaFuncSetAttribute(flash_kernel, cudaFuncAttributeMaxDynamicSharedMemorySize, FA_SMEM_BYTES);

    split3<<<2048, 256>>>(x,  x3,  MM, 0);
    split3<<<1024, 256>>>(wq, w3q, DD, 1);
    split3<<<1024, 256>>>(wk, w3k, DD, 1);
    split3<<<1024, 256>>>(wv, w3v, DD, 1);
    split3<<<1024, 256>>>(wo, w3o, DD, 1);

    hgemm<0><<<dim3(DD / 128, MM / 128, 3), 256, HG_SMEM>>>(
        x3, w3q, w3k, w3v, bq, bk, bv, q, k, v);

    flash_kernel<<<dim3(SS / 64, BB * HH), 256, FA_SMEM_BYTES>>>();

    split3<<<2048, 256>>>(attn, a3, MM, 0);
    hgemm<1><<<dim3(DD / 128, MM / 128, 1), 256, HG_SMEM>>>(
        a3, w3o, w3o, w3o, bo, bo, bo, out, out, out);
}

// round 13
// speedup vs baseline: 2.9042x; 1.7971x over previous
#include <cuda_runtime.h>
#include <cuda_bf16.h>
#include <cstdint>
#include <math.h>

// ---------------------------------------------------------------------------
// Problem constants
// ---------------------------------------------------------------------------
#define BB  2
#define SS  2048
#define DD  2048
#define HH  16
#define DHH 128
#define MM  (BB*SS)          // 4096
#define KP  6144             // tripled K for split-bf16
#define KP2 (KP*2)           // row stride in bytes
#define RSCALE 0.08838834764831843f

// ---------------------------------------------------------------------------
// Scratch (device globals — no allocation allowed)
// ---------------------------------------------------------------------------
__device__ float g_attn[MM*DD];
__device__ __nv_bfloat16 g_x3[(size_t)MM*KP];   // x split  [hi|hi|lo]
__device__ __nv_bfloat16 g_w3q[(size_t)DD*KP];  // weights  [hi|lo|hi]
__device__ __nv_bfloat16 g_w3k[(size_t)DD*KP];
__device__ __nv_bfloat16 g_w3v[(size_t)DD*KP];
__device__ __nv_bfloat16 g_w3o[(size_t)DD*KP];
__device__ __nv_bfloat16 g_a3[(size_t)MM*KP];   // attn split [hi|hi|lo]
// attention operands (bf16 split), produced by hgemm<0> epilogue
__device__ __nv_bfloat16 g_qh[(size_t)BB*HH*SS*DHH];   // [b,h,s,dh]
__device__ __nv_bfloat16 g_ql[(size_t)BB*HH*SS*DHH];
__device__ __nv_bfloat16 g_kh[(size_t)BB*HH*SS*DHH];
__device__ __nv_bfloat16 g_kl[(size_t)BB*HH*SS*DHH];
__device__ __nv_bfloat16 g_vth[(size_t)BB*HH*SS*DHH];  // [b,h,dh,s]  (transposed)
__device__ __nv_bfloat16 g_vtl[(size_t)BB*HH*SS*DHH];

// ---------------------------------------------------------------------------
// PTX helpers — ONLY non-'a' features (ldmatrix, mma.sync, cp.async)
// ---------------------------------------------------------------------------
__device__ __forceinline__ uint32_t smem_to_u32(const void* p) {
    uint32_t a;
    asm("{ .reg .u64 t; cvta.to.shared.u64 t, %1; cvt.u32.u64 %0, t; }"
        : "=r"(a) : "l"(p));
    return a;
}
#define CP_ASYNC16(dst, src) \
    asm volatile("cp.async.cg.shared.global [%0], [%1], 16;" :: "r"(dst), "l"(src))
#define CP_COMMIT() asm volatile("cp.async.commit_group;" ::: "memory")
#define CP_WAIT1()  asm volatile("cp.async.wait_group 1;" ::: "memory")
#define CP_WAIT0()  asm volatile("cp.async.wait_group 0;" ::: "memory")
#define LDSM_X4(r0,r1,r2,r3,addr) \
    asm volatile("ldmatrix.sync.aligned.m8n8.x4.shared.b16 {%0,%1,%2,%3},[%4];" \
        : "=r"(r0),"=r"(r1),"=r"(r2),"=r"(r3) : "r"(addr))
#define LDSM_X2(r0,r1,addr) \
    asm volatile("ldmatrix.sync.aligned.m8n8.x2.shared.b16 {%0,%1},[%2];" \
        : "=r"(r0),"=r"(r1) : "r"(addr))
#define MMA16816(d,a0,a1,a2,a3,b0,b1) \
    asm volatile("mma.sync.aligned.m16n8k16.row.col.f32.bf16.bf16.f32 " \
        "{%0,%1,%2,%3},{%4,%5,%6,%7},{%8,%9},{%0,%1,%2,%3};" \
        : "+f"((d)[0]),"+f"((d)[1]),"+f"((d)[2]),"+f"((d)[3]) \
        : "r"(a0),"r"(a1),"r"(a2),"r"(a3),"r"(b0),"r"(b1))

__device__ __forceinline__ uint32_t bf16pack(__nv_bfloat16 a, __nv_bfloat16 b) {
    unsigned short x = *(unsigned short*)&a, y = *(unsigned short*)&b;
    return (uint32_t)x | ((uint32_t)y << 16);
}
// split two fp32 into packed bf16x2 hi and lo parts
__device__ __forceinline__ void split_pack(float x, float y, uint32_t& h, uint32_t& l) {
    __nv_bfloat16 hx = __float2bfloat16(x);
    __nv_bfloat16 hy = __float2bfloat16(y);
    __nv_bfloat16 lx = __float2bfloat16(x - __bfloat162float(hx));
    __nv_bfloat16 ly = __float2bfloat16(y - __bfloat162float(hy));
    h = bf16pack(hx, hy);
    l = bf16pack(lx, ly);
}

// ---------------------------------------------------------------------------
// Split pre-pass: fp32 [rows, 2048] -> bf16 [rows, 6144].
// bmode 0 (A side): [hi | hi | lo].  bmode 1 (B side): [hi | lo | hi].
// ---------------------------------------------------------------------------
__global__ void split3(const float* __restrict__ src, __nv_bfloat16* __restrict__ dst,
                       int rows, int bmode)
{
    int idx = blockIdx.x * blockDim.x + threadIdx.x;
    int total = rows * (DD / 4);
    for (; idx < total; idx += gridDim.x * blockDim.x) {
        int r  = idx >> 9;
        int c4 = (idx & 511) * 4;
        float4 v = *(const float4*)(src + (size_t)r * DD + c4);
        union { __nv_bfloat16 b[4]; uint64_t u; } H, L;
        H.b[0] = __float2bfloat16(v.x);
        H.b[1] = __float2bfloat16(v.y);
        H.b[2] = __float2bfloat16(v.z);
        H.b[3] = __float2bfloat16(v.w);
        L.b[0] = __float2bfloat16(v.x - __bfloat162float(H.b[0]));
        L.b[1] = __float2bfloat16(v.y - __bfloat162float(H.b[1]));
        L.b[2] = __float2bfloat16(v.z - __bfloat162float(H.b[2]));
        L.b[3] = __float2bfloat16(v.w - __bfloat162float(H.b[3]));
        __nv_bfloat16* row = dst + (size_t)r * KP;
        *(uint64_t*)&row[c4]        = H.u;
        *(uint64_t*)&row[2048 + c4] = bmode ? L.u : H.u;
        *(uint64_t*)&row[4096 + c4] = bmode ? H.u : L.u;
    }
}

// ---------------------------------------------------------------------------
// HMMA GEMM (validated R10): C = A3 @ W3^T + bias.
// MODE 0: epilogue splits result to bf16 hi/lo attention operands
//         (z=0 -> qh/ql, z=1 -> kh/kl, z=2 -> vth/vtl TRANSPOSED).
// MODE 1: plain fp32 [M,N] store.
// ---------------------------------------------------------------------------
#define NIT 192
#define STG_BYTES (128*40*2)            // 10240
#define SB_OFF    (3*STG_BYTES)
#define BIAS_OFF  (6*STG_BYTES)
#define HG_SMEM   (BIAS_OFF + 512)

template<int MODE>
__global__ __launch_bounds__(256) void hgemm(
    const __nv_bfloat16* __restrict__ A3,
    const __nv_bfloat16* __restrict__ W0, const __nv_bfloat16* __restrict__ W1,
    const __nv_bfloat16* __restrict__ W2,
    const float* __restrict__ b0, const float* __restrict__ b1, const float* __restrict__ b2,
    float* __restrict__ C,
    __nv_bfloat16* __restrict__ qh, __nv_bfloat16* __restrict__ ql,
    __nv_bfloat16* __restrict__ kh, __nv_bfloat16* __restrict__ kl,
    __nv_bfloat16* __restrict__ vth, __nv_bfloat16* __restrict__ vtl)
{
    extern __shared__ char smem[];
    const int tid  = threadIdx.x;
    const int wid  = tid >> 5, lane = tid & 31;
    const int wm   = wid >> 2;
    const int wn   = wid & 3;
    const int bn   = blockIdx.x * 128;
    const int bm   = blockIdx.y * 128;
    const int z    = blockIdx.z;
    const __nv_bfloat16* W = (z == 0) ? W0 : (z == 1) ? W1 : W2;
    const float* bias      = (z == 0) ? b0 : (z == 1) ? b1 : b2;

    const uint32_t sbase = smem_to_u32(smem);
    float* sBias = (float*)(smem + BIAS_OFF);
    if (tid < 128) sBias[tid] = bias[bn + tid];

    const char* Abase = (const char*)(A3 + (size_t)bm * KP);
    const char* Wbase = (const char*)(W  + (size_t)bn * KP);

    auto issue = [&](int it, int stg) {
        #pragma unroll
        for (int half = 0; half < 2; half++) {
            int idx = tid + half * 256;
            int row = idx >> 2;
            int seg = idx & 3;
            uint32_t da = sbase + stg * STG_BYTES + row * 80 + seg * 16;
            CP_ASYNC16(da, Abase + (size_t)row * KP2 + (size_t)it * 64 + seg * 16);
            uint32_t db = sbase + SB_OFF + stg * STG_BYTES + row * 80 + seg * 16;
            CP_ASYNC16(db, Wbase + (size_t)row * KP2 + (size_t)it * 64 + seg * 16);
        }
    };

    float acc[4][4][4];
    #pragma unroll
    for (int i = 0; i < 4; i++)
        #pragma unroll
        for (int j = 0; j < 4; j++)
            #pragma unroll
            for (int r = 0; r < 4; r++) acc[i][j][r] = 0.f;

    issue(0, 0); CP_COMMIT();
    issue(1, 1); CP_COMMIT();

    const int a_row = lane & 15;
    const int a_coff = (lane >> 4) << 3;
    const int b_row = lane & 7;
    const int b_coff = ((lane >> 3) & 1) << 3;

    for (int it = 0; it < NIT; it++) {
        CP_WAIT1();
        __syncthreads();
        if (it + 2 < NIT) issue(it + 2, (it + 2) % 3);
        CP_COMMIT();

        const int stg = it % 3;
        const uint32_t aS = sbase + stg * STG_BYTES;
        const uint32_t bS = sbase + SB_OFF + stg * STG_BYTES;

        #pragma unroll
        for (int ks = 0; ks < 2; ks++) {
            uint32_t a[4][4], b[4][2];
            #pragma unroll
            for (int mi = 0; mi < 4; mi++) {
                uint32_t addr = aS + (wm * 64 + mi * 16 + a_row) * 80
                              + (ks * 16 + a_coff) * 2;
                LDSM_X4(a[mi][0], a[mi][1], a[mi][2], a[mi][3], addr);
            }
            #pragma unroll
            for (int ni = 0; ni < 4; ni++) {
                uint32_t addr = bS + (wn * 32 + ni * 8 + b_row) * 80
                              + (ks * 16 + b_coff) * 2;
                LDSM_X2(b[ni][0], b[ni][1], addr);
            }
            #pragma unroll
            for (int mi = 0; mi < 4; mi++)
                #pragma unroll
                for (int ni = 0; ni < 4; ni++)
                    MMA16816(acc[mi][ni], a[mi][0], a[mi][1], a[mi][2], a[mi][3],
                             b[ni][0], b[ni][1]);
        }
        __syncthreads();
    }

    // epilogue
    const int erow = lane >> 2;
    const int ecol = (lane & 3) * 2;
    #pragma unroll
    for (int mi = 0; mi < 4; mi++) {
        #pragma unroll
        for (int ni = 0; ni < 4; ni++) {
            int nloc = wn * 32 + ni * 8 + ecol;
            int n = bn + nloc;
            float bia0 = sBias[nloc], bia1 = sBias[nloc + 1];
            #pragma unroll
            for (int half = 0; half < 2; half++) {
                int m = bm + wm * 64 + mi * 16 + erow + half * 8;
                float v0 = acc[mi][ni][half * 2]     + bia0;
                float v1 = acc[mi][ni][half * 2 + 1] + bia1;
                if (MODE == 0) {
                    int b_ = m >> 11, s_ = m & 2047, h = n >> 7, dh = n & 127;
                    uint32_t ph, pl;
                    split_pack(v0, v1, ph, pl);
                    if (z <= 1) {
                        __nv_bfloat16* H = (z == 0) ? qh : kh;
                        __nv_bfloat16* L = (z == 0) ? ql : kl;
                        size_t base = ((size_t)(b_ * HH + h) * SS + s_) * DHH + dh;
                        *(uint32_t*)&H[base] = ph;
                        *(uint32_t*)&L[base] = pl;
                    } else {
                        // V transposed: [b,h,dh,s]
                        size_t tb = ((size_t)(b_ * HH + h) * DHH + dh) * SS + s_;
                        __nv_bfloat16 h0 = __float2bfloat16(v0);
                        __nv_bfloat16 h1 = __float2bfloat16(v1);
                        vth[tb]      = h0;
                        vth[tb + SS] = h1;
                        vtl[tb]      = __float2bfloat16(v0 - __bfloat162float(h0));
                        vtl[tb + SS] = __float2bfloat16(v1 - __bfloat162float(h1));
                    }
                } else {
                    float2 v = make_float2(v0, v1);
                    *(float2*)&C[(size_t)m * DD + n] = v;
                }
            }
        }
    }
}

// ---------------------------------------------------------------------------
// Flash attention, mma.sync, split-bf16 (causal).
// Br=128, Bc=64, 256 threads (8 warps, each owns m16 rows).
// S = Qh.Kh^T + Qh.Kl^T + Ql.Kh^T ;  O += Ph.Vh + Ph.Vl + Pl.Vh
// V is pre-transposed in gmem ([b,h,dh,s]) -> non-trans ldmatrix B operand.
// ---------------------------------------------------------------------------
#define FQSTR 272   // Q/K smem row stride bytes (136 bf16)
#define FVSTR 144   // Vt smem row stride bytes (72 bf16)
#define SM_QH 0
#define SM_QL 34816
#define SM_KH 69632
#define SM_KL 87040
#define SM_VH 104448
#define SM_VL 122880
#define FLASH_SMEM 141312

__global__ __launch_bounds__(256) void flash_mma()
{
    extern __shared__ char fsm[];
    const uint32_t sb = smem_to_u32(fsm);
    const int tid  = threadIdx.x;
    const int wid  = tid >> 5, lane = tid & 31;
    const int qt   = blockIdx.x;
    const int bh   = blockIdx.y;
    const int q0   = qt * 128;

    const char* Qh = (const char*)(g_qh + (size_t)bh * SS * DHH);
    const char* Ql = (const char*)(g_ql + (size_t)bh * SS * DHH);
    const char* Kh = (const char*)(g_kh + (size_t)bh * SS * DHH);
    const char* Kl = (const char*)(g_kl + (size_t)bh * SS * DHH);
    const char* Vh = (const char*)(g_vth + (size_t)bh * SS * DHH);  // [dh][s]
    const char* Vl = (const char*)(g_vtl + (size_t)bh * SS * DHH);

    // Q tile load (once): 128 rows x 256B, 2 arrays
    #pragma unroll
    for (int i = 0; i < 8; i++) {
        int idx = tid + i * 256;        // 0..2047
        int row = idx >> 4;             // 0..127
        int seg = idx & 15;
        size_t g = ((size_t)(q0 + row) * DHH + seg * 8) * 2;
        CP_ASYNC16(sb + SM_QH + row * FQSTR + seg * 16, Qh + g);
        CP_ASYNC16(sb + SM_QL + row * FQSTR + seg * 16, Ql + g);
    }
    CP_COMMIT();

    float O[16][4];
    #pragma unroll
    for (int nb = 0; nb < 16; nb++)
        #pragma unroll
        for (int r = 0; r < 4; r++) O[nb][r] = 0.f;
    float m0 = -1e30f, m1 = -1e30f, l0 = 0.f, l1 = 0.f;

    const int arow  = lane & 15;
    const int acoff = (lane >> 4) << 3;
    const int brow  = lane & 7;
    const int bcoff = ((lane >> 3) & 1) << 3;
    const int ktmax = 2 * qt + 2;

    for (int kt = 0; kt < ktmax; kt++) {
        const int kc0 = kt * 64;
        // K tiles: 64 rows x 256B x2 ; V tiles: 128 rows x 128B x2
        #pragma unroll
        for (int i = 0; i < 4; i++) {
            int idx = tid + i * 256;            // 0..1023
            int krow = idx >> 4, kseg = idx & 15;
            size_t gk = ((size_t)(kc0 + krow) * DHH + kseg * 8) * 2;
            CP_ASYNC16(sb + SM_KH + krow * FQSTR + kseg * 16, Kh + gk);
            CP_ASYNC16(sb + SM_KL + krow * FQSTR + kseg * 16, Kl + gk);
            int vrow = idx >> 3, vseg = idx & 7;
            size_t gv = ((size_t)vrow * SS + kc0 + vseg * 8) * 2;
            CP_ASYNC16(sb + SM_VH + vrow * FVSTR + vseg * 16, Vh + gv);
            CP_ASYNC16(sb + SM_VL + vrow * FVSTR + vseg * 16, Vl + gv);
        }
        CP_COMMIT();
        CP_WAIT0();
        __syncthreads();

        // ---- S = Q K^T (split 3-term), warp computes m16 x n64
        float s[8][4];
        #pragma unroll
        for (int j = 0; j < 8; j++)
            #pragma unroll
            for (int r = 0; r < 4; r++) s[j][r] = 0.f;

        #pragma unroll
        for (int kc = 0; kc < 8; kc++) {
            uint32_t aqh[4], aql[4];
            uint32_t qaddr = sb + SM_QH + (wid * 16 + arow) * FQSTR + (kc * 16 + acoff) * 2;
            LDSM_X4(aqh[0], aqh[1], aqh[2], aqh[3], qaddr);
            LDSM_X4(aql[0], aql[1], aql[2], aql[3], qaddr + (SM_QL - SM_QH));
            #pragma unroll
            for (int j = 0; j < 8; j++) {
                uint32_t kb0, kb1, kl0, kl1;
                uint32_t kaddr = sb + SM_KH + (j * 8 + brow) * FQSTR + (kc * 16 + bcoff) * 2;
                LDSM_X2(kb0, kb1, kaddr);
                LDSM_X2(kl0, kl1, kaddr + (SM_KL - SM_KH));
                MMA16816(s[j], aqh[0], aqh[1], aqh[2], aqh[3], kb0, kb1);
                MMA16816(s[j], aqh[0], aqh[1], aqh[2], aqh[3], kl0, kl1);
                MMA16816(s[j], aql[0], aql[1], aql[2], aql[3], kb0, kb1);
            }
        }

        #pragma unroll
        for (int j = 0; j < 8; j++)
            #pragma unroll
            for (int r = 0; r < 4; r++) s[j][r] *= RSCALE;

        // causal mask (only the two diagonal-overlapping tiles)
        if (kt >= 2 * qt) {
            int row0 = q0 + wid * 16 + (lane >> 2);
            #pragma unroll
            for (int j = 0; j < 8; j++) {
                int col = kc0 + j * 8 + 2 * (lane & 3);
                if (col     > row0)     s[j][0] = -1e30f;
                if (col + 1 > row0)     s[j][1] = -1e30f;
                if (col     > row0 + 8) s[j][2] = -1e30f;
                if (col + 1 > row0 + 8) s[j][3] = -1e30f;
            }
        }

        // ---- online softmax (rows lane>>2 and +8, replicated across quad)
        float rm0 = -1e30f, rm1 = -1e30f;
        #pragma unroll
        for (int j = 0; j < 8; j++) {
            rm0 = fmaxf(rm0, fmaxf(s[j][0], s[j][1]));
            rm1 = fmaxf(rm1, fmaxf(s[j][2], s[j][3]));
        }
        rm0 = fmaxf(rm0, __shfl_xor_sync(0xffffffffu, rm0, 1));
        rm0 = fmaxf(rm0, __shfl_xor_sync(0xffffffffu, rm0, 2));
        rm1 = fmaxf(rm1, __shfl_xor_sync(0xffffffffu, rm1, 1));
        rm1 = fmaxf(rm1, __shfl_xor_sync(0xffffffffu, rm1, 2));

        float nm0 = fmaxf(m0, rm0), nm1 = fmaxf(m1, rm1);
        float f0 = __expf(m0 - nm0), f1 = __expf(m1 - nm1);
        float sum0 = 0.f, sum1 = 0.f;
        #pragma unroll
        for (int j = 0; j < 8; j++) {
            s[j][0] = __expf(s[j][0] - nm0);
            s[j][1] = __expf(s[j][1] - nm0);
            s[j][2] = __expf(s[j][2] - nm1);
            s[j][3] = __expf(s[j][3] - nm1);
            sum0 += s[j][0] + s[j][1];
            sum1 += s[j][2] + s[j][3];
        }
        sum0 += __shfl_xor_sync(0xffffffffu, sum0, 1);
        sum0 += __shfl_xor_sync(0xffffffffu, sum0, 2);
        sum1 += __shfl_xor_sync(0xffffffffu, sum1, 1);
        sum1 += __shfl_xor_sync(0xffffffffu, sum1, 2);
        l0 = l0 * f0 + sum0;  m0 = nm0;
        l1 = l1 * f1 + sum1;  m1 = nm1;

        #pragma unroll
        for (int nb = 0; nb < 16; nb++) {
            O[nb][0] *= f0; O[nb][1] *= f0;
            O[nb][2] *= f1; O[nb][3] *= f1;
        }

        // ---- pack P into A fragments (hi/lo)
        uint32_t ah[4][4], al[4][4];
        #pragma unroll
        for (int t = 0; t < 4; t++) {
            split_pack(s[2*t][0],   s[2*t][1],   ah[t][0], al[t][0]);
            split_pack(s[2*t][2],   s[2*t][3],   ah[t][1], al[t][1]);
            split_pack(s[2*t+1][0], s[2*t+1][1], ah[t][2], al[t][2]);
            split_pack(s[2*t+1][2], s[2*t+1][3], ah[t][3], al[t][3]);
        }

        // ---- O += P V (split 3-term), n = 128 dh
        #pragma unroll
        for (int nb = 0; nb < 16; nb++) {
            #pragma unroll
            for (int t = 0; t < 4; t++) {
                uint32_t vb0, vb1, vl0, vl1;
                uint32_t vaddr = sb + SM_VH + (nb * 8 + brow) * FVSTR + (t * 16 + bcoff) * 2;
                LDSM_X2(vb0, vb1, vaddr);
                LDSM_X2(vl0, vl1, vaddr + (SM_VL - SM_VH));
                MMA16816(O[nb], ah[t][0], ah[t][1], ah[t][2], ah[t][3], vb0, vb1);
                MMA16816(O[nb], ah[t][0], ah[t][1], ah[t][2], ah[t][3], vl0, vl1);
                MMA16816(O[nb], al[t][0], al[t][1], al[t][2], al[t][3], vb0, vb1);
            }
        }
        __syncthreads();
    }

    // ---- epilogue: normalize, write g_attn [b*s, d] fp32
    const int b_ = bh >> 4;
    const int h_ = bh & 15;
    const float inv0 = 1.f / l0, inv1 = 1.f / l1;
    const int r0 = q0 + wid * 16 + (lane >> 2);
    #pragma unroll
    for (int nb = 0; nb < 16; nb++) {
        int col = nb * 8 + 2 * (lane & 3);
        size_t base0 = ((size_t)(b_ * SS + r0)) * DD + h_ * DHH + col;
        size_t base1 = ((size_t)(b_ * SS + r0 + 8)) * DD + h_ * DHH + col;
        *(float2*)&g_attn[base0] = make_float2(O[nb][0] * inv0, O[nb][1] * inv0);
        *(float2*)&g_attn[base1] = make_float2(O[nb][2] * inv1, O[nb][3] * inv1);
    }
}

// ---------------------------------------------------------------------------
// Launch
// ---------------------------------------------------------------------------
extern "C" void kernel_launch(void* const* d_in, const int* in_sizes, int n_in,
                              void* d_out, int out_size)
{
    (void)in_sizes; (void)n_in; (void)out_size;
    const float* x  = (const float*)d_in[0];
    const float* wq = (const float*)d_in[2];
    const float* bq = (const float*)d_in[3];
    const float* wk = (const float*)d_in[4];
    const float* bk = (const float*)d_in[5];
    const float* wv = (const float*)d_in[6];
    const float* bv = (const float*)d_in[7];
    const float* wo = (const float*)d_in[8];
    const float* bo = (const float*)d_in[9];
    float* out = (float*)d_out;

    float* attn;
    __nv_bfloat16 *x3, *w3q, *w3k, *w3v, *w3o, *a3;
    __nv_bfloat16 *qh, *ql, *kh, *kl, *vth, *vtl;
    cudaGetSymbolAddress((void**)&attn, g_attn);
    cudaGetSymbolAddress((void**)&x3,   g_x3);
    cudaGetSymbolAddress((void**)&w3q,  g_w3q);
    cudaGetSymbolAddress((void**)&w3k,  g_w3k);
    cudaGetSymbolAddress((void**)&w3v,  g_w3v);
    cudaGetSymbolAddress((void**)&w3o,  g_w3o);
    cudaGetSymbolAddress((void**)&a3,   g_a3);
    cudaGetSymbolAddress((void**)&qh,   g_qh);
    cudaGetSymbolAddress((void**)&ql,   g_ql);
    cudaGetSymbolAddress((void**)&kh,   g_kh);
    cudaGetSymbolAddress((void**)&kl,   g_kl);
    cudaGetSymbolAddress((void**)&vth,  g_vth);
    cudaGetSymbolAddress((void**)&vtl,  g_vtl);

    cudaFuncSetAttribute(hgemm<0>, cudaFuncAttributeMaxDynamicSharedMemorySize, HG_SMEM);
    cudaFuncSetAttribute(hgemm<1>, cudaFuncAttributeMaxDynamicSharedMemorySize, HG_SMEM);
    cudaFuncSetAttribute(flash_mma, cudaFuncAttributeMaxDynamicSharedMemorySize, FLASH_SMEM);

    split3<<<2048, 256>>>(x,  x3,  MM, 0);
    split3<<<1024, 256>>>(wq, w3q, DD, 1);
    split3<<<1024, 256>>>(wk, w3k, DD, 1);
    split3<<<1024, 256>>>(wv, w3v, DD, 1);
    split3<<<1024, 256>>>(wo, w3o, DD, 1);

    hgemm<0><<<dim3(DD / 128, MM / 128, 3), 256, HG_SMEM>>>(
        x3, w3q, w3k, w3v, bq, bk, bv, nullptr,
        qh, ql, kh, kl, vth, vtl);

    flash_mma<<<dim3(SS / 128, BB * HH), 256, FLASH_SMEM>>>();

    split3<<<2048, 256>>>(attn, a3, MM, 0);
    hgemm<1><<<dim3(DD / 128, MM / 128, 1), 256, HG_SMEM>>>(
        a3, w3o, w3o, w3o, bo, bo, bo, out,
        nullptr, nullptr, nullptr, nullptr, nullptr, nullptr);
}

// round 14
// speedup vs baseline: 3.3371x; 1.1491x over previous
#include <cuda_runtime.h>
#include <cuda_bf16.h>
#include <cstdint>
#include <math.h>

// ---------------------------------------------------------------------------
// Problem constants
// ---------------------------------------------------------------------------
#define BB  2
#define SS  2048
#define DD  2048
#define HH  16
#define DHH 128
#define MM  (BB*SS)          // 4096
#define KP  6144             // tripled K for split-bf16
#define KP2 (KP*2)           // row stride in bytes
#define RSCALE 0.08838834764831843f

// ---------------------------------------------------------------------------
// Scratch (device globals — no allocation allowed)
// ---------------------------------------------------------------------------
__device__ __nv_bfloat16 g_x3[(size_t)MM*KP];   // x split  [hi|hi|lo]
__device__ __nv_bfloat16 g_w3q[(size_t)DD*KP];  // weights  [hi|lo|hi]
__device__ __nv_bfloat16 g_w3k[(size_t)DD*KP];
__device__ __nv_bfloat16 g_w3v[(size_t)DD*KP];
__device__ __nv_bfloat16 g_w3o[(size_t)DD*KP];
__device__ __nv_bfloat16 g_a3[(size_t)MM*KP];   // attn split [hi|hi|lo] (written by flash)
// attention operands (bf16 split), produced by hgemm<0> epilogue
__device__ __nv_bfloat16 g_qh[(size_t)BB*HH*SS*DHH];   // [b,h,s,dh]
__device__ __nv_bfloat16 g_ql[(size_t)BB*HH*SS*DHH];
__device__ __nv_bfloat16 g_kh[(size_t)BB*HH*SS*DHH];
__device__ __nv_bfloat16 g_kl[(size_t)BB*HH*SS*DHH];
__device__ __nv_bfloat16 g_vth[(size_t)BB*HH*SS*DHH];  // [b,h,dh,s]  (transposed)
__device__ __nv_bfloat16 g_vtl[(size_t)BB*HH*SS*DHH];

// ---------------------------------------------------------------------------
// PTX helpers — ONLY non-'a' features (ldmatrix, mma.sync, cp.async)
// ---------------------------------------------------------------------------
__device__ __forceinline__ uint32_t smem_to_u32(const void* p) {
    uint32_t a;
    asm("{ .reg .u64 t; cvta.to.shared.u64 t, %1; cvt.u32.u64 %0, t; }"
        : "=r"(a) : "l"(p));
    return a;
}
#define CP_ASYNC16(dst, src) \
    asm volatile("cp.async.cg.shared.global [%0], [%1], 16;" :: "r"(dst), "l"(src))
#define CP_COMMIT() asm volatile("cp.async.commit_group;" ::: "memory")
#define CP_WAIT1()  asm volatile("cp.async.wait_group 1;" ::: "memory")
#define CP_WAIT0()  asm volatile("cp.async.wait_group 0;" ::: "memory")
#define LDSM_X4(r0,r1,r2,r3,addr) \
    asm volatile("ldmatrix.sync.aligned.m8n8.x4.shared.b16 {%0,%1,%2,%3},[%4];" \
        : "=r"(r0),"=r"(r1),"=r"(r2),"=r"(r3) : "r"(addr))
#define LDSM_X2(r0,r1,addr) \
    asm volatile("ldmatrix.sync.aligned.m8n8.x2.shared.b16 {%0,%1},[%2];" \
        : "=r"(r0),"=r"(r1) : "r"(addr))
#define MMA16816(d,a0,a1,a2,a3,b0,b1) \
    asm volatile("mma.sync.aligned.m16n8k16.row.col.f32.bf16.bf16.f32 " \
        "{%0,%1,%2,%3},{%4,%5,%6,%7},{%8,%9},{%0,%1,%2,%3};" \
        : "+f"((d)[0]),"+f"((d)[1]),"+f"((d)[2]),"+f"((d)[3]) \
        : "r"(a0),"r"(a1),"r"(a2),"r"(a3),"r"(b0),"r"(b1))

__device__ __forceinline__ uint32_t bf16pack(__nv_bfloat16 a, __nv_bfloat16 b) {
    unsigned short x = *(unsigned short*)&a, y = *(unsigned short*)&b;
    return (uint32_t)x | ((uint32_t)y << 16);
}
// split two fp32 into packed bf16x2 hi and lo parts
__device__ __forceinline__ void split_pack(float x, float y, uint32_t& h, uint32_t& l) {
    __nv_bfloat16 hx = __float2bfloat16(x);
    __nv_bfloat16 hy = __float2bfloat16(y);
    __nv_bfloat16 lx = __float2bfloat16(x - __bfloat162float(hx));
    __nv_bfloat16 ly = __float2bfloat16(y - __bfloat162float(hy));
    h = bf16pack(hx, hy);
    l = bf16pack(lx, ly);
}

// ---------------------------------------------------------------------------
// Split pre-pass: fp32 [rows, 2048] -> bf16 [rows, 6144].
// bmode 0 (A side): [hi | hi | lo].  bmode 1 (B side): [hi | lo | hi].
// ---------------------------------------------------------------------------
__global__ void split3(const float* __restrict__ src, __nv_bfloat16* __restrict__ dst,
                       int rows, int bmode)
{
    int idx = blockIdx.x * blockDim.x + threadIdx.x;
    int total = rows * (DD / 4);
    for (; idx < total; idx += gridDim.x * blockDim.x) {
        int r  = idx >> 9;
        int c4 = (idx & 511) * 4;
        float4 v = *(const float4*)(src + (size_t)r * DD + c4);
        union { __nv_bfloat16 b[4]; uint64_t u; } H, L;
        H.b[0] = __float2bfloat16(v.x);
        H.b[1] = __float2bfloat16(v.y);
        H.b[2] = __float2bfloat16(v.z);
        H.b[3] = __float2bfloat16(v.w);
        L.b[0] = __float2bfloat16(v.x - __bfloat162float(H.b[0]));
        L.b[1] = __float2bfloat16(v.y - __bfloat162float(H.b[1]));
        L.b[2] = __float2bfloat16(v.z - __bfloat162float(H.b[2]));
        L.b[3] = __float2bfloat16(v.w - __bfloat162float(H.b[3]));
        __nv_bfloat16* row = dst + (size_t)r * KP;
        *(uint64_t*)&row[c4]        = H.u;
        *(uint64_t*)&row[2048 + c4] = bmode ? L.u : H.u;
        *(uint64_t*)&row[4096 + c4] = bmode ? H.u : L.u;
    }
}

// ---------------------------------------------------------------------------
// HMMA GEMM: C = A3 @ W3^T + bias.  BM=BN=128, BK=64, 256 threads.
// 3-stage cp.async pipeline, ONE __syncthreads per iteration.
// MODE 0: epilogue splits to bf16 hi/lo attention operands
//         (z=0 -> qh/ql, z=1 -> kh/kl, z=2 -> vth/vtl TRANSPOSED).
// MODE 1: plain fp32 [M,N] store.
// ---------------------------------------------------------------------------
#define NIT2 96                 // KP / 64
#define ROWB 144                // padded row stride (128B data + 16B pad)
#define ARR_BYTES (128*ROWB)    // 18432 per array per stage
#define STG2 (2*ARR_BYTES)      // 36864 (A + B)
#define BIAS_OFF (3*STG2)       // 110592
#define HG_SMEM (BIAS_OFF + 512)

template<int MODE>
__global__ __launch_bounds__(256) void hgemm(
    const __nv_bfloat16* __restrict__ A3,
    const __nv_bfloat16* __restrict__ W0, const __nv_bfloat16* __restrict__ W1,
    const __nv_bfloat16* __restrict__ W2,
    const float* __restrict__ b0, const float* __restrict__ b1, const float* __restrict__ b2,
    float* __restrict__ C,
    __nv_bfloat16* __restrict__ qh, __nv_bfloat16* __restrict__ ql,
    __nv_bfloat16* __restrict__ kh, __nv_bfloat16* __restrict__ kl,
    __nv_bfloat16* __restrict__ vth, __nv_bfloat16* __restrict__ vtl)
{
    extern __shared__ char smem[];
    const int tid  = threadIdx.x;
    const int wid  = tid >> 5, lane = tid & 31;
    const int wm   = wid >> 2;
    const int wn   = wid & 3;
    const int bn   = blockIdx.x * 128;
    const int bm   = blockIdx.y * 128;
    const int z    = blockIdx.z;
    const __nv_bfloat16* W = (z == 0) ? W0 : (z == 1) ? W1 : W2;
    const float* bias      = (z == 0) ? b0 : (z == 1) ? b1 : b2;

    const uint32_t sbase = smem_to_u32(smem);
    float* sBias = (float*)(smem + BIAS_OFF);
    if (tid < 128) sBias[tid] = bias[bn + tid];

    const char* Abase = (const char*)(A3 + (size_t)bm * KP);
    const char* Wbase = (const char*)(W  + (size_t)bn * KP);

    // per stage: A 128 rows x 128B (8 x 16B segs), B same; 8 cp.async/thread
    auto issue = [&](int it, int stg) {
        #pragma unroll
        for (int i = 0; i < 4; i++) {
            int chunk = tid + i * 256;            // 0..1023
            int row = chunk >> 3;
            int seg = chunk & 7;
            uint32_t da = sbase + stg * STG2 + row * ROWB + seg * 16;
            CP_ASYNC16(da, Abase + (size_t)row * KP2 + (size_t)it * 128 + seg * 16);
            uint32_t db = da + ARR_BYTES;
            CP_ASYNC16(db, Wbase + (size_t)row * KP2 + (size_t)it * 128 + seg * 16);
        }
    };

    float acc[4][4][4];
    #pragma unroll
    for (int i = 0; i < 4; i++)
        #pragma unroll
        for (int j = 0; j < 4; j++)
            #pragma unroll
            for (int r = 0; r < 4; r++) acc[i][j][r] = 0.f;

    issue(0, 0); CP_COMMIT();
    issue(1, 1); CP_COMMIT();

    const int a_row = lane & 15;
    const int a_coff = (lane >> 4) << 3;
    const int b_row = lane & 7;
    const int b_coff = ((lane >> 3) & 1) << 3;

    for (int it = 0; it < NIT2; it++) {
        CP_WAIT1();
        __syncthreads();   // stage it%3 ready; all warps past compute(it-1)
        if (it + 2 < NIT2) { issue(it + 2, (it + 2) % 3); }
        CP_COMMIT();

        const int stg = it % 3;
        const uint32_t aS = sbase + stg * STG2;
        const uint32_t bS = aS + ARR_BYTES;

        #pragma unroll
        for (int ks = 0; ks < 4; ks++) {
            uint32_t a[4][4], b[4][2];
            #pragma unroll
            for (int mi = 0; mi < 4; mi++) {
                uint32_t addr = aS + (wm * 64 + mi * 16 + a_row) * ROWB
                              + (ks * 16 + a_coff) * 2;
                LDSM_X4(a[mi][0], a[mi][1], a[mi][2], a[mi][3], addr);
            }
            #pragma unroll
            for (int ni = 0; ni < 4; ni++) {
                uint32_t addr = bS + (wn * 32 + ni * 8 + b_row) * ROWB
                              + (ks * 16 + b_coff) * 2;
                LDSM_X2(b[ni][0], b[ni][1], addr);
            }
            #pragma unroll
            for (int mi = 0; mi < 4; mi++)
                #pragma unroll
                for (int ni = 0; ni < 4; ni++)
                    MMA16816(acc[mi][ni], a[mi][0], a[mi][1], a[mi][2], a[mi][3],
                             b[ni][0], b[ni][1]);
        }
        // no trailing sync: next iteration's top sync protects stage reuse
    }

    // epilogue
    const int erow = lane >> 2;
    const int ecol = (lane & 3) * 2;
    #pragma unroll
    for (int mi = 0; mi < 4; mi++) {
        #pragma unroll
        for (int ni = 0; ni < 4; ni++) {
            int nloc = wn * 32 + ni * 8 + ecol;
            int n = bn + nloc;
            float bia0 = sBias[nloc], bia1 = sBias[nloc + 1];
            #pragma unroll
            for (int half = 0; half < 2; half++) {
                int m = bm + wm * 64 + mi * 16 + erow + half * 8;
                float v0 = acc[mi][ni][half * 2]     + bia0;
                float v1 = acc[mi][ni][half * 2 + 1] + bia1;
                if (MODE == 0) {
                    int b_ = m >> 11, s_ = m & 2047, h = n >> 7, dh = n & 127;
                    uint32_t ph, pl;
                    split_pack(v0, v1, ph, pl);
                    if (z <= 1) {
                        __nv_bfloat16* H = (z == 0) ? qh : kh;
                        __nv_bfloat16* L = (z == 0) ? ql : kl;
                        size_t base = ((size_t)(b_ * HH + h) * SS + s_) * DHH + dh;
                        *(uint32_t*)&H[base] = ph;
                        *(uint32_t*)&L[base] = pl;
                    } else {
                        // V transposed: [b,h,dh,s]
                        size_t tb = ((size_t)(b_ * HH + h) * DHH + dh) * SS + s_;
                        __nv_bfloat16 h0 = __float2bfloat16(v0);
                        __nv_bfloat16 h1 = __float2bfloat16(v1);
                        vth[tb]      = h0;
                        vth[tb + SS] = h1;
                        vtl[tb]      = __float2bfloat16(v0 - __bfloat162float(h0));
                        vtl[tb + SS] = __float2bfloat16(v1 - __bfloat162float(h1));
                    }
                } else {
                    float2 v = make_float2(v0, v1);
                    *(float2*)&C[(size_t)m * DD + n] = v;
                }
            }
        }
    }
}

// ---------------------------------------------------------------------------
// Flash attention, mma.sync, split-bf16 (causal). (validated R13)
// Epilogue now writes g_a3 directly in [hi|hi|lo] triple layout,
// eliminating the fp32 g_attn round trip + split3 pass.
// ---------------------------------------------------------------------------
#define FQSTR 272   // Q/K smem row stride bytes (136 bf16)
#define FVSTR 144   // Vt smem row stride bytes (72 bf16)
#define SM_QH 0
#define SM_QL 34816
#define SM_KH 69632
#define SM_KL 87040
#define SM_VH 104448
#define SM_VL 122880
#define FLASH_SMEM 141312

__global__ __launch_bounds__(256) void flash_mma()
{
    extern __shared__ char fsm[];
    const uint32_t sb = smem_to_u32(fsm);
    const int tid  = threadIdx.x;
    const int wid  = tid >> 5, lane = tid & 31;
    const int qt   = blockIdx.x;
    const int bh   = blockIdx.y;
    const int q0   = qt * 128;

    const char* Qh = (const char*)(g_qh + (size_t)bh * SS * DHH);
    const char* Ql = (const char*)(g_ql + (size_t)bh * SS * DHH);
    const char* Kh = (const char*)(g_kh + (size_t)bh * SS * DHH);
    const char* Kl = (const char*)(g_kl + (size_t)bh * SS * DHH);
    const char* Vh = (const char*)(g_vth + (size_t)bh * SS * DHH);  // [dh][s]
    const char* Vl = (const char*)(g_vtl + (size_t)bh * SS * DHH);

    // Q tile load (once): 128 rows x 256B, 2 arrays
    #pragma unroll
    for (int i = 0; i < 8; i++) {
        int idx = tid + i * 256;        // 0..2047
        int row = idx >> 4;             // 0..127
        int seg = idx & 15;
        size_t g = ((size_t)(q0 + row) * DHH + seg * 8) * 2;
        CP_ASYNC16(sb + SM_QH + row * FQSTR + seg * 16, Qh + g);
        CP_ASYNC16(sb + SM_QL + row * FQSTR + seg * 16, Ql + g);
    }
    CP_COMMIT();

    float O[16][4];
    #pragma unroll
    for (int nb = 0; nb < 16; nb++)
        #pragma unroll
        for (int r = 0; r < 4; r++) O[nb][r] = 0.f;
    float m0 = -1e30f, m1 = -1e30f, l0 = 0.f, l1 = 0.f;

    const int arow  = lane & 15;
    const int acoff = (lane >> 4) << 3;
    const int brow  = lane & 7;
    const int bcoff = ((lane >> 3) & 1) << 3;
    const int ktmax = 2 * qt + 2;

    for (int kt = 0; kt < ktmax; kt++) {
        const int kc0 = kt * 64;
        // K tiles: 64 rows x 256B x2 ; V tiles: 128 rows x 128B x2
        #pragma unroll
        for (int i = 0; i < 4; i++) {
            int idx = tid + i * 256;            // 0..1023
            int krow = idx >> 4, kseg = idx & 15;
            size_t gk = ((size_t)(kc0 + krow) * DHH + kseg * 8) * 2;
            CP_ASYNC16(sb + SM_KH + krow * FQSTR + kseg * 16, Kh + gk);
            CP_ASYNC16(sb + SM_KL + krow * FQSTR + kseg * 16, Kl + gk);
            int vrow = idx >> 3, vseg = idx & 7;
            size_t gv = ((size_t)vrow * SS + kc0 + vseg * 8) * 2;
            CP_ASYNC16(sb + SM_VH + vrow * FVSTR + vseg * 16, Vh + gv);
            CP_ASYNC16(sb + SM_VL + vrow * FVSTR + vseg * 16, Vl + gv);
        }
        CP_COMMIT();
        CP_WAIT0();
        __syncthreads();

        // ---- S = Q K^T (split 3-term), warp computes m16 x n64
        float s[8][4];
        #pragma unroll
        for (int j = 0; j < 8; j++)
            #pragma unroll
            for (int r = 0; r < 4; r++) s[j][r] = 0.f;

        #pragma unroll
        for (int kc = 0; kc < 8; kc++) {
            uint32_t aqh[4], aql[4];
            uint32_t qaddr = sb + SM_QH + (wid * 16 + arow) * FQSTR + (kc * 16 + acoff) * 2;
            LDSM_X4(aqh[0], aqh[1], aqh[2], aqh[3], qaddr);
            LDSM_X4(aql[0], aql[1], aql[2], aql[3], qaddr + (SM_QL - SM_QH));
            #pragma unroll
            for (int j = 0; j < 8; j++) {
                uint32_t kb0, kb1, kl0, kl1;
                uint32_t kaddr = sb + SM_KH + (j * 8 + brow) * FQSTR + (kc * 16 + bcoff) * 2;
                LDSM_X2(kb0, kb1, kaddr);
                LDSM_X2(kl0, kl1, kaddr + (SM_KL - SM_KH));
                MMA16816(s[j], aqh[0], aqh[1], aqh[2], aqh[3], kb0, kb1);
                MMA16816(s[j], aqh[0], aqh[1], aqh[2], aqh[3], kl0, kl1);
                MMA16816(s[j], aql[0], aql[1], aql[2], aql[3], kb0, kb1);
            }
        }

        #pragma unroll
        for (int j = 0; j < 8; j++)
            #pragma unroll
            for (int r = 0; r < 4; r++) s[j][r] *= RSCALE;

        // causal mask (only the two diagonal-overlapping tiles)
        if (kt >= 2 * qt) {
            int row0 = q0 + wid * 16 + (lane >> 2);
            #pragma unroll
            for (int j = 0; j < 8; j++) {
                int col = kc0 + j * 8 + 2 * (lane & 3);
                if (col     > row0)     s[j][0] = -1e30f;
                if (col + 1 > row0)     s[j][1] = -1e30f;
                if (col     > row0 + 8) s[j][2] = -1e30f;
                if (col + 1 > row0 + 8) s[j][3] = -1e30f;
            }
        }

        // ---- online softmax (rows lane>>2 and +8, replicated across quad)
        float rm0 = -1e30f, rm1 = -1e30f;
        #pragma unroll
        for (int j = 0; j < 8; j++) {
            rm0 = fmaxf(rm0, fmaxf(s[j][0], s[j][1]));
            rm1 = fmaxf(rm1, fmaxf(s[j][2], s[j][3]));
        }
        rm0 = fmaxf(rm0, __shfl_xor_sync(0xffffffffu, rm0, 1));
        rm0 = fmaxf(rm0, __shfl_xor_sync(0xffffffffu, rm0, 2));
        rm1 = fmaxf(rm1, __shfl_xor_sync(0xffffffffu, rm1, 1));
        rm1 = fmaxf(rm1, __shfl_xor_sync(0xffffffffu, rm1, 2));

        float nm0 = fmaxf(m0, rm0), nm1 = fmaxf(m1, rm1);
        float f0 = __expf(m0 - nm0), f1 = __expf(m1 - nm1);
        float sum0 = 0.f, sum1 = 0.f;
        #pragma unroll
        for (int j = 0; j < 8; j++) {
            s[j][0] = __expf(s[j][0] - nm0);
            s[j][1] = __expf(s[j][1] - nm0);
            s[j][2] = __expf(s[j][2] - nm1);
            s[j][3] = __expf(s[j][3] - nm1);
            sum0 += s[j][0] + s[j][1];
            sum1 += s[j][2] + s[j][3];
        }
        sum0 += __shfl_xor_sync(0xffffffffu, sum0, 1);
        sum0 += __shfl_xor_sync(0xffffffffu, sum0, 2);
        sum1 += __shfl_xor_sync(0xffffffffu, sum1, 1);
        sum1 += __shfl_xor_sync(0xffffffffu, sum1, 2);
        l0 = l0 * f0 + sum0;  m0 = nm0;
        l1 = l1 * f1 + sum1;  m1 = nm1;

        #pragma unroll
        for (int nb = 0; nb < 16; nb++) {
            O[nb][0] *= f0; O[nb][1] *= f0;
            O[nb][2] *= f1; O[nb][3] *= f1;
        }

        // ---- pack P into A fragments (hi/lo)
        uint32_t ah[4][4], al[4][4];
        #pragma unroll
        for (int t = 0; t < 4; t++) {
            split_pack(s[2*t][0],   s[2*t][1],   ah[t][0], al[t][0]);
            split_pack(s[2*t][2],   s[2*t][3],   ah[t][1], al[t][1]);
            split_pack(s[2*t+1][0], s[2*t+1][1], ah[t][2], al[t][2]);
            split_pack(s[2*t+1][2], s[2*t+1][3], ah[t][3], al[t][3]);
        }

        // ---- O += P V (split 3-term), n = 128 dh
        #pragma unroll
        for (int nb = 0; nb < 16; nb++) {
            #pragma unroll
            for (int t = 0; t < 4; t++) {
                uint32_t vb0, vb1, vl0, vl1;
                uint32_t vaddr = sb + SM_VH + (nb * 8 + brow) * FVSTR + (t * 16 + bcoff) * 2;
                LDSM_X2(vb0, vb1, vaddr);
                LDSM_X2(vl0, vl1, vaddr + (SM_VL - SM_VH));
                MMA16816(O[nb], ah[t][0], ah[t][1], ah[t][2], ah[t][3], vb0, vb1);
                MMA16816(O[nb], ah[t][0], ah[t][1], ah[t][2], ah[t][3], vl0, vl1);
                MMA16816(O[nb], al[t][0], al[t][1], al[t][2], al[t][3], vb0, vb1);
            }
        }
        __syncthreads();
    }

    // ---- epilogue: normalize, split, write g_a3 [m, 6144] = [hi|hi|lo]
    const int b_ = bh >> 4;
    const int h_ = bh & 15;
    const float inv0 = 1.f / l0, inv1 = 1.f / l1;
    const int r0 = q0 + wid * 16 + (lane >> 2);
    #pragma unroll
    for (int nb = 0; nb < 16; nb++) {
        int col = nb * 8 + 2 * (lane & 3);
        size_t row0 = (size_t)(b_ * SS + r0) * KP + h_ * DHH + col;
        size_t row1 = (size_t)(b_ * SS + r0 + 8) * KP + h_ * DHH + col;
        uint32_t ph, pl;
        split_pack(O[nb][0] * inv0, O[nb][1] * inv0, ph, pl);
        *(uint32_t*)&g_a3[row0]        = ph;
        *(uint32_t*)&g_a3[row0 + 2048] = ph;
        *(uint32_t*)&g_a3[row0 + 4096] = pl;
        split_pack(O[nb][2] * inv1, O[nb][3] * inv1, ph, pl);
        *(uint32_t*)&g_a3[row1]        = ph;
        *(uint32_t*)&g_a3[row1 + 2048] = ph;
        *(uint32_t*)&g_a3[row1 + 4096] = pl;
    }
}

// ---------------------------------------------------------------------------
// Launch
// ---------------------------------------------------------------------------
extern "C" void kernel_launch(void* const* d_in, const int* in_sizes, int n_in,
                              void* d_out, int out_size)
{
    (void)in_sizes; (void)n_in; (void)out_size;
    const float* x  = (const float*)d_in[0];
    const float* wq = (const float*)d_in[2];
    const float* bq = (const float*)d_in[3];
    const float* wk = (const float*)d_in[4];
    const float* bk = (const float*)d_in[5];
    const float* wv = (const float*)d_in[6];
    const float* bv = (const float*)d_in[7];
    const float* wo = (const float*)d_in[8];
    const float* bo = (const float*)d_in[9];
    float* out = (float*)d_out;

    __nv_bfloat16 *x3, *w3q, *w3k, *w3v, *w3o, *a3;
    __nv_bfloat16 *qh, *ql, *kh, *kl, *vth, *vtl;
    cudaGetSymbolAddress((void**)&x3,   g_x3);
    cudaGetSymbolAddress((void**)&w3q,  g_w3q);
    cudaGetSymbolAddress((void**)&w3k,  g_w3k);
    cudaGetSymbolAddress((void**)&w3v,  g_w3v);
    cudaGetSymbolAddress((void**)&w3o,  g_w3o);
    cudaGetSymbolAddress((void**)&a3,   g_a3);
    cudaGetSymbolAddress((void**)&qh,   g_qh);
    cudaGetSymbolAddress((void**)&ql,   g_ql);
    cudaGetSymbolAddress((void**)&kh,   g_kh);
    cudaGetSymbolAddress((void**)&kl,   g_kl);
    cudaGetSymbolAddress((void**)&vth,  g_vth);
    cudaGetSymbolAddress((void**)&vtl,  g_vtl);

    cudaFuncSetAttribute(hgemm<0>, cudaFuncAttributeMaxDynamicSharedMemorySize, HG_SMEM);
    cudaFuncSetAttribute(hgemm<1>, cudaFuncAttributeMaxDynamicSharedMemorySize, HG_SMEM);
    cudaFuncSetAttribute(flash_mma, cudaFuncAttributeMaxDynamicSharedMemorySize, FLASH_SMEM);

    split3<<<2048, 256>>>(x,  x3,  MM, 0);
    split3<<<1024, 256>>>(wq, w3q, DD, 1);
    split3<<<1024, 256>>>(wk, w3k, DD, 1);
    split3<<<1024, 256>>>(wv, w3v, DD, 1);
    split3<<<1024, 256>>>(wo, w3o, DD, 1);

    hgemm<0><<<dim3(DD / 128, MM / 128, 3), 256, HG_SMEM>>>(
        x3, w3q, w3k, w3v, bq, bk, bv, nullptr,
        qh, ql, kh, kl, vth, vtl);

    flash_mma<<<dim3(SS / 128, BB * HH), 256, FLASH_SMEM>>>();

    hgemm<1><<<dim3(DD / 128, MM / 128, 1), 256, HG_SMEM>>>(
        a3, w3o, w3o, w3o, bo, bo, bo, out,
        nullptr, nullptr, nullptr, nullptr, nullptr, nullptr);
}